// round 11
// baseline (speedup 1.0000x reference)
#include <cuda_runtime.h>

#define BATCH 8
#define SEQ   4096
#define EMB   512
#define HD    64

typedef unsigned long long u64;

// ---- packed fp32x2 helpers (sm_103a FFMA2 path) ----
__device__ __forceinline__ void ffma2(u64& d, u64 a, u64 b) {
    asm("fma.rn.f32x2 %0, %1, %2, %0;" : "+l"(d) : "l"(a), "l"(b));
}
__device__ __forceinline__ u64 mul2(u64 a, u64 b) {
    u64 d; asm("mul.rn.f32x2 %0, %1, %2;" : "=l"(d) : "l"(a), "l"(b));
    return d;
}
__device__ __forceinline__ u64 splat2(float x) {
    u64 d; asm("mov.b64 %0, {%1, %1};" : "=l"(d) : "f"(x));
    return d;
}
__device__ __forceinline__ float hadd2(u64 v) {
    float lo, hi;
    asm("mov.b64 {%0, %1}, %2;" : "=f"(lo), "=f"(hi) : "l"(v));
    return lo + hi;
}
__device__ __forceinline__ float2 unpack2(u64 v) {
    float2 f;
    asm("mov.b64 {%0, %1}, %2;" : "=f"(f.x), "=f"(f.y) : "l"(v));
    return f;
}

// scratch for q, k, v (__device__ globals, allocation-free)
__device__ float g_q[BATCH * SEQ * HD];
__device__ float g_k[BATCH * SEQ * HD];
__device__ float g_v[BATCH * SEQ * HD];

// ---------------------------------------------------------------------------
// Fused QKV projection with FFMA2: x[32768,512] @ {Wq,Wk,Wv}[512,64]
// Thread tile 4 rows x 4 cols per matrix; packed over output-col pairs.
// ---------------------------------------------------------------------------
__global__ __launch_bounds__(256) void qkv_proj(
    const float* __restrict__ x,
    const float* __restrict__ Wq,
    const float* __restrict__ Wk,
    const float* __restrict__ Wv)
{
    __shared__ float As[64 * 32];
    __shared__ float Ws[3 * 32 * 64];

    const int tid = threadIdx.x;
    const int ty = tid >> 4, tx = tid & 15;
    const long row0 = (long)blockIdx.x * 64;

    u64 acc[3][4][2];
#pragma unroll
    for (int m = 0; m < 3; m++)
#pragma unroll
        for (int i = 0; i < 4; i++) {
            acc[m][i][0] = 0ull; acc[m][i][1] = 0ull;
        }

    for (int kb = 0; kb < EMB; kb += 32) {
#pragma unroll
        for (int l = 0; l < 2; l++) {
            int idx = tid + l * 256;
            int r = idx >> 3, kg = idx & 7;
            *(float4*)&As[r * 32 + kg * 4] =
                *(const float4*)&x[(row0 + r) * EMB + kb + kg * 4];
        }
#pragma unroll
        for (int l = 0; l < 6; l++) {
            int idx = tid + l * 256;
            int m = idx >> 9;
            int rem = idx & 511;
            int r = rem >> 4, c4 = rem & 15;
            const float* w = (m == 0) ? Wq : ((m == 1) ? Wk : Wv);
            *(float4*)&Ws[(m * 32 + r) * 64 + c4 * 4] =
                *(const float4*)&w[(kb + r) * HD + c4 * 4];
        }
        __syncthreads();

#pragma unroll 4
        for (int k = 0; k < 32; k++) {
            u64 as[4];
#pragma unroll
            for (int i = 0; i < 4; i++)
                as[i] = splat2(As[(4 * ty + i) * 32 + k]);
#pragma unroll
            for (int m = 0; m < 3; m++) {
                ulonglong2 w = *(const ulonglong2*)&Ws[(m * 32 + k) * 64 + tx * 4];
#pragma unroll
                for (int i = 0; i < 4; i++) {
                    ffma2(acc[m][i][0], as[i], w.x);
                    ffma2(acc[m][i][1], as[i], w.y);
                }
            }
        }
        __syncthreads();
    }

#pragma unroll
    for (int i = 0; i < 4; i++) {
        long r = row0 + 4 * ty + i;
        float* dst[3] = {g_q, g_k, g_v};
#pragma unroll
        for (int m = 0; m < 3; m++) {
            float2 a = unpack2(acc[m][i][0]);
            float2 b = unpack2(acc[m][i][1]);
            *(float4*)&dst[m][r * HD + tx * 4] = make_float4(a.x, a.y, b.x, b.y);
        }
    }
}

// ---------------------------------------------------------------------------
// Flash-attention (fp32, causal) with FFMA2.
// Block handles q-tile pair {bx, 63-bx} -> exactly 65 k-tile units (balanced).
// Thread (ty,tx): S rows 4ty..4ty+3, S cols {tx, tx+16, tx+32, tx+48};
// O cols {tx, tx+16, tx+32, tx+48}. Both GEMMs packed over the reduction
// dim (h for S, j for PV); V stored transposed so PV needs no splats.
// ---------------------------------------------------------------------------
#define ST 68   // padded stride: 16B-aligned, 16B-bank delta of 17 == 1 mod 8

__global__ __launch_bounds__(256, 2) void attn(float* __restrict__ out)
{
    extern __shared__ float sm[];
    float* Qs = sm;              // [64][ST]  row = q-row, h contiguous
    float* Ks = Qs + 64 * ST;    // [64][ST]  row = k-row, h contiguous
    float* Vt = Ks + 64 * ST;    // [64][ST]  row = head col h, j contiguous
    float* Ps = Vt + 64 * ST;    // [64][ST]  row = q-row, j contiguous

    const int tid = threadIdx.x;
    const int ty = tid >> 4, tx = tid & 15;
    const int b = blockIdx.y;
    const float cfac = 0.06379864817f;   // 512^-0.5 * log2(e)

#pragma unroll 1
    for (int half = 0; half < 2; half++) {
        const int qi = half ? (63 - (int)blockIdx.x) : (int)blockIdx.x;
        const long qbase = ((long)b * SEQ + (long)qi * 64) * HD;

        __syncthreads();   // prior half's S reads of Qs complete
#pragma unroll
        for (int l = 0; l < 4; l++) {
            int idx = tid + l * 256;
            int r = idx >> 4, h4 = (idx & 15) * 4;
            *(float4*)&Qs[r * ST + h4] =
                *(const float4*)&g_q[qbase + r * HD + h4];
        }

        float mrow[4], lrow[4];
        u64 o2[4][4];
#pragma unroll
        for (int i = 0; i < 4; i++) {
            mrow[i] = -3.0e38f;
            lrow[i] = 0.f;
#pragma unroll
            for (int j = 0; j < 4; j++) o2[i][j] = 0ull;
        }

        for (int kt = 0; kt <= qi; kt++) {
            __syncthreads();   // prior iter done reading Ks/Vt/Ps
            const long kbase = ((long)b * SEQ + (long)kt * 64) * HD;

            // K tile: row-major, h contiguous
#pragma unroll
            for (int l = 0; l < 4; l++) {
                int idx = tid + l * 256;
                int c = idx >> 4, h4 = (idx & 15) * 4;
                *(float4*)&Ks[c * ST + h4] =
                    *(const float4*)&g_k[kbase + c * HD + h4];
            }
            // V tile transposed: Vt[h][j], j contiguous
            {
                int jg = (tid >> 4) * 4;        // 4 consecutive key rows
                int h4 = (tid & 15) * 4;        // 4 consecutive head cols
                float4 v0 = *(const float4*)&g_v[kbase + (jg + 0) * HD + h4];
                float4 v1 = *(const float4*)&g_v[kbase + (jg + 1) * HD + h4];
                float4 v2 = *(const float4*)&g_v[kbase + (jg + 2) * HD + h4];
                float4 v3 = *(const float4*)&g_v[kbase + (jg + 3) * HD + h4];
                *(float4*)&Vt[(h4 + 0) * ST + jg] = make_float4(v0.x, v1.x, v2.x, v3.x);
                *(float4*)&Vt[(h4 + 1) * ST + jg] = make_float4(v0.y, v1.y, v2.y, v3.y);
                *(float4*)&Vt[(h4 + 2) * ST + jg] = make_float4(v0.z, v1.z, v2.z, v3.z);
                *(float4*)&Vt[(h4 + 3) * ST + jg] = make_float4(v0.w, v1.w, v2.w, v3.w);
            }
            __syncthreads();

            // ---- S = Q K^T, packed over h ----
            u64 sp[4][4];
#pragma unroll
            for (int i = 0; i < 4; i++)
#pragma unroll
                for (int j = 0; j < 4; j++) sp[i][j] = 0ull;

            const float* qb = &Qs[(4 * ty) * ST];
            const float* kb = &Ks[tx * ST];
#pragma unroll 1
            for (int h = 0; h < HD; h += 4) {
                ulonglong2 q[4], k[4];
#pragma unroll
                for (int i = 0; i < 4; i++)
                    q[i] = *(const ulonglong2*)&qb[i * ST + h];
#pragma unroll
                for (int j = 0; j < 4; j++)
                    k[j] = *(const ulonglong2*)&kb[j * 16 * ST + h];
#pragma unroll
                for (int i = 0; i < 4; i++)
#pragma unroll
                    for (int j = 0; j < 4; j++) {
                        ffma2(sp[i][j], q[i].x, k[j].x);
                        ffma2(sp[i][j], q[i].y, k[j].y);
                    }
            }

            // ---- scale + causal mask + online softmax (log2 domain) ----
            const bool diag = (kt == qi);
#pragma unroll
            for (int i = 0; i < 4; i++) {
                const int rloc = 4 * ty + i;
                float s[4];
#pragma unroll
                for (int j = 0; j < 4; j++) {
                    float v = hadd2(sp[i][j]) * cfac;
                    if (diag && (tx + 16 * j) > rloc) v = -1e30f;
                    s[j] = v;
                }
                float mx = fmaxf(fmaxf(s[0], s[1]), fmaxf(s[2], s[3]));
#pragma unroll
                for (int off = 8; off >= 1; off >>= 1)
                    mx = fmaxf(mx, __shfl_xor_sync(0xffffffffu, mx, off));
                const float mnew = fmaxf(mrow[i], mx);
                const float corr = exp2f(mrow[i] - mnew);
                float rs = 0.f;
#pragma unroll
                for (int j = 0; j < 4; j++) {
                    float p = exp2f(s[j] - mnew);
                    s[j] = p;
                    rs += p;
                }
#pragma unroll
                for (int off = 8; off >= 1; off >>= 1)
                    rs += __shfl_xor_sync(0xffffffffu, rs, off);
                lrow[i] = lrow[i] * corr + rs;
                mrow[i] = mnew;
                const u64 c2 = splat2(corr);
#pragma unroll
                for (int j = 0; j < 4; j++) o2[i][j] = mul2(o2[i][j], c2);
                // write P (row-major, j contiguous)
#pragma unroll
                for (int j = 0; j < 4; j++)
                    Ps[rloc * ST + tx + 16 * j] = s[j];
            }
            __syncthreads();

            // ---- O += P V, packed over j (V transposed: no splats) ----
            const float* pb = &Ps[(4 * ty) * ST];
            const float* vb = &Vt[tx * ST];
#pragma unroll 1
            for (int j = 0; j < 64; j += 4) {
                ulonglong2 p[4], v[4];
#pragma unroll
                for (int i = 0; i < 4; i++)
                    p[i] = *(const ulonglong2*)&pb[i * ST + j];
#pragma unroll
                for (int c = 0; c < 4; c++)
                    v[c] = *(const ulonglong2*)&vb[c * 16 * ST + j];
#pragma unroll
                for (int i = 0; i < 4; i++)
#pragma unroll
                    for (int c = 0; c < 4; c++) {
                        ffma2(o2[i][c], p[i].x, v[c].x);
                        ffma2(o2[i][c], p[i].y, v[c].y);
                    }
            }
        }

        // ---- epilogue: horizontal add, normalize, store ----
#pragma unroll
        for (int i = 0; i < 4; i++) {
            const float inv = 1.0f / lrow[i];
            long r = (long)b * SEQ + (long)qi * 64 + 4 * ty + i;
#pragma unroll
            for (int c = 0; c < 4; c++)
                out[r * HD + tx + 16 * c] = hadd2(o2[i][c]) * inv;
        }
    }
}

// ---------------------------------------------------------------------------
extern "C" void kernel_launch(void* const* d_in, const int* in_sizes, int n_in,
                              void* d_out, int out_size)
{
    const float* x  = (const float*)d_in[0];
    const float* Wq = (const float*)d_in[1];
    const float* Wk = (const float*)d_in[2];
    const float* Wv = (const float*)d_in[3];
    float* out = (float*)d_out;

    const int attn_smem = 4 * 64 * ST * (int)sizeof(float);   // 69632 B
    cudaFuncSetAttribute(attn, cudaFuncAttributeMaxDynamicSharedMemorySize,
                         attn_smem);

    qkv_proj<<<(BATCH * SEQ) / 64, 256>>>(x, Wq, Wk, Wv);
    attn<<<dim3(32, BATCH), 256, attn_smem>>>(out);
}

// round 14
// speedup vs baseline: 2.1120x; 2.1120x over previous
#include <cuda_runtime.h>
#include <cuda_bf16.h>

#define BATCH 8
#define SEQ   4096
#define EMB   512
#define HD    64

typedef unsigned int u32;
typedef unsigned short u16;

// bf16 hi/lo split operands (device globals, allocation-free). All row-major [t][h].
__device__ __nv_bfloat16 g_qh[BATCH * SEQ * HD];
__device__ __nv_bfloat16 g_ql[BATCH * SEQ * HD];
__device__ __nv_bfloat16 g_kh[BATCH * SEQ * HD];
__device__ __nv_bfloat16 g_kl[BATCH * SEQ * HD];
__device__ __nv_bfloat16 g_vh[BATCH * SEQ * HD];
__device__ __nv_bfloat16 g_vl[BATCH * SEQ * HD];

// ---------------- helpers ----------------
__device__ __forceinline__ u32 s2u(const void* p) {
    u32 a;
    asm("{ .reg .u64 t; cvta.to.shared.u64 t, %1; cvt.u32.u64 %0, t; }"
        : "=r"(a) : "l"(p));
    return a;
}
__device__ __forceinline__ void ldsm4(u32* r, u32 addr) {
    asm volatile("ldmatrix.sync.aligned.m8n8.x4.shared.b16 {%0,%1,%2,%3}, [%4];"
        : "=r"(r[0]), "=r"(r[1]), "=r"(r[2]), "=r"(r[3]) : "r"(addr));
}
__device__ __forceinline__ void ldsm4t(u32* r, u32 addr) {
    asm volatile("ldmatrix.sync.aligned.m8n8.x4.trans.shared.b16 {%0,%1,%2,%3}, [%4];"
        : "=r"(r[0]), "=r"(r[1]), "=r"(r[2]), "=r"(r[3]) : "r"(addr));
}
__device__ __forceinline__ void mma16816(float* c, const u32* a, const u32* b) {
    asm volatile(
        "mma.sync.aligned.m16n8k16.row.col.f32.bf16.bf16.f32 "
        "{%0,%1,%2,%3}, {%4,%5,%6,%7}, {%8,%9}, {%0,%1,%2,%3};"
        : "+f"(c[0]), "+f"(c[1]), "+f"(c[2]), "+f"(c[3])
        : "r"(a[0]), "r"(a[1]), "r"(a[2]), "r"(a[3]), "r"(b[0]), "r"(b[1]));
}
// pack two floats into bf16x2 hi, return hi; residual pair in lo
__device__ __forceinline__ u32 packhl(float a, float b, u32& lo) {
    __nv_bfloat162 h = __floats2bfloat162_rn(a, b);
    __nv_bfloat162 l = __floats2bfloat162_rn(a - __bfloat162float(h.x),
                                             b - __bfloat162float(h.y));
    lo = *(u32*)&l;
    return *(u32*)&h;
}

// ---------------------------------------------------------------------------
// Fused QKV projection (scalar fp32, proven) + bf16 hi/lo row-major epilogue.
// ---------------------------------------------------------------------------
__global__ __launch_bounds__(256) void qkv_proj(
    const float* __restrict__ x,
    const float* __restrict__ Wq,
    const float* __restrict__ Wk,
    const float* __restrict__ Wv)
{
    __shared__ float As[64 * 32];
    __shared__ float Ws[3 * 32 * 64];

    const int tid = threadIdx.x;
    const int ty = tid >> 4, tx = tid & 15;
    const long row0 = (long)blockIdx.x * 64;

    float acc[3][4][4];
#pragma unroll
    for (int m = 0; m < 3; m++)
#pragma unroll
        for (int i = 0; i < 4; i++)
#pragma unroll
            for (int j = 0; j < 4; j++) acc[m][i][j] = 0.f;

    for (int kb = 0; kb < EMB; kb += 32) {
#pragma unroll
        for (int l = 0; l < 2; l++) {
            int idx = tid + l * 256;
            int r = idx >> 3, kg = idx & 7;
            *(float4*)&As[r * 32 + kg * 4] =
                *(const float4*)&x[(row0 + r) * EMB + kb + kg * 4];
        }
#pragma unroll
        for (int l = 0; l < 6; l++) {
            int idx = tid + l * 256;
            int m = idx >> 9;
            int rem = idx & 511;
            int r = rem >> 4, c4 = rem & 15;
            const float* w = (m == 0) ? Wq : ((m == 1) ? Wk : Wv);
            *(float4*)&Ws[(m * 32 + r) * 64 + c4 * 4] =
                *(const float4*)&w[(kb + r) * HD + c4 * 4];
        }
        __syncthreads();

#pragma unroll
        for (int k = 0; k < 32; k++) {
            float a[4];
#pragma unroll
            for (int i = 0; i < 4; i++) a[i] = As[(4 * ty + i) * 32 + k];
#pragma unroll
            for (int m = 0; m < 3; m++) {
                float4 w = *(float4*)&Ws[(m * 32 + k) * 64 + tx * 4];
#pragma unroll
                for (int i = 0; i < 4; i++) {
                    acc[m][i][0] = fmaf(a[i], w.x, acc[m][i][0]);
                    acc[m][i][1] = fmaf(a[i], w.y, acc[m][i][1]);
                    acc[m][i][2] = fmaf(a[i], w.z, acc[m][i][2]);
                    acc[m][i][3] = fmaf(a[i], w.w, acc[m][i][3]);
                }
            }
        }
        __syncthreads();
    }

    __nv_bfloat16* H[3] = {g_qh, g_kh, g_vh};
    __nv_bfloat16* L[3] = {g_ql, g_kl, g_vl};
#pragma unroll
    for (int i = 0; i < 4; i++) {
        long r = row0 + 4 * ty + i;
#pragma unroll
        for (int m = 0; m < 3; m++) {
            u32 l01, l23;
            u32 h01 = packhl(acc[m][i][0], acc[m][i][1], l01);
            u32 h23 = packhl(acc[m][i][2], acc[m][i][3], l23);
            *(uint2*)&H[m][r * HD + tx * 4] = make_uint2(h01, h23);
            *(uint2*)&L[m][r * HD + tx * 4] = make_uint2(l01, l23);
        }
    }
}

// ---------------------------------------------------------------------------
// Flash attention on HMMA (mma.sync m16n8k16 bf16, split hi/lo 3x).
// CTA = 128 threads (4 warps), Q-tile 64 (16 rows/warp), K-tile 64.
// Grid (32, 8): block handles q-tiles {bx, 63-bx} of batch b -> 65 k-tiles.
// No-max softmax (scores bounded): O accumulates in registers all the way.
// SMEM tiles SW128-swizzled: off(r,c16) = r*128 + ((c16 ^ (r&7)) << 4).
// ---------------------------------------------------------------------------
__global__ __launch_bounds__(128) void attn(float* __restrict__ out)
{
    __shared__ __align__(128) __nv_bfloat16 sKh[64 * 64];
    __shared__ __align__(128) __nv_bfloat16 sKl[64 * 64];
    __shared__ __align__(128) __nv_bfloat16 sVh[64 * 64];
    __shared__ __align__(128) __nv_bfloat16 sVl[64 * 64];

    const int tid = threadIdx.x;
    const int w = tid >> 5, lane = tid & 31;
    const int g = lane >> 2, tig = lane & 3;
    const int b = blockIdx.y, bx = blockIdx.x;
    const float cfac = 0.06375871655f;   // 512^-0.5 * log2(e), exact

    const u32 kh_b = s2u(sKh), kl_b = s2u(sKl);
    const u32 vh_b = s2u(sVh), vl_b = s2u(sVl);

#pragma unroll 1
    for (int half = 0; half < 2; half++) {
        const int qi = half ? (63 - bx) : bx;
        const size_t qr0 = (size_t)b * SEQ + (size_t)qi * 64 + w * 16;

        // ---- Q A-frags straight from gmem (regs for the whole half) ----
        u32 qh[4][4], ql[4][4];
#pragma unroll
        for (int kc = 0; kc < 4; kc++)
#pragma unroll
            for (int rr = 0; rr < 4; rr++) {
                size_t row = qr0 + g + (rr & 1) * 8;
                int col = kc * 16 + (rr >> 1) * 8 + 2 * tig;
                qh[kc][rr] = *(const u32*)&g_qh[row * HD + col];
                ql[kc][rr] = *(const u32*)&g_ql[row * HD + col];
            }

        float of[8][4];
#pragma unroll
        for (int jn = 0; jn < 8; jn++)
#pragma unroll
            for (int r = 0; r < 4; r++) of[jn][r] = 0.f;
        float l0 = 0.f, l1 = 0.f;

#pragma unroll 1
        for (int kt = 0; kt <= qi; kt++) {
            __syncthreads();
            // ---- load K/V hi/lo tiles into swizzled SMEM ----
            const size_t kb = (size_t)b * SEQ + (size_t)kt * 64;
#pragma unroll
            for (int l = 0; l < 4; l++) {
                int idx = tid + l * 128;
                int row = idx >> 3, c = idx & 7;
                u32 d = (u32)row * 128 + (u32)((c ^ (row & 7)) << 4);
                const size_t s = (kb + row) * HD + c * 8;
                *(uint4*)((char*)sKh + d) = *(const uint4*)&g_kh[s];
                *(uint4*)((char*)sKl + d) = *(const uint4*)&g_kl[s];
                *(uint4*)((char*)sVh + d) = *(const uint4*)&g_vh[s];
                *(uint4*)((char*)sVl + d) = *(const uint4*)&g_vl[s];
            }
            __syncthreads();

            const bool dg = (kt == qi);
            u32 ph[4][4], pl[4][4];

            // ---- S = Qh*Kh + Qh*Kl + Ql*Kh ; fused softmax ; pack P ----
#pragma unroll
            for (int j = 0; j < 8; j++) {
                float s[4] = {0.f, 0.f, 0.f, 0.f};
                u32 bh[8], bl[8];
                {
                    u32 row = (u32)(j * 8 + (lane & 7));
                    u32 c16 = (u32)(lane >> 3);
                    u32 o1 = row * 128 + (((c16) ^ (row & 7)) << 4);
                    u32 o2 = row * 128 + (((c16 + 4) ^ (row & 7)) << 4);
                    ldsm4(bh, kh_b + o1);
                    ldsm4(bh + 4, kh_b + o2);
                    ldsm4(bl, kl_b + o1);
                    ldsm4(bl + 4, kl_b + o2);
                }
#pragma unroll
                for (int kc = 0; kc < 4; kc++) {
                    mma16816(s, qh[kc], bh + 2 * kc);
                    mma16816(s, qh[kc], bl + 2 * kc);
                    mma16816(s, ql[kc], bh + 2 * kc);
                }
                float p[4];
#pragma unroll
                for (int r = 0; r < 4; r++) {
                    float pv = exp2f(s[r] * cfac);
                    if (dg) {
                        int key = j * 8 + 2 * tig + (r & 1);
                        int qrl = w * 16 + g + ((r >> 1) << 3);
                        if (key > qrl) pv = 0.f;
                    }
                    p[r] = pv;
                }
                l0 += p[0] + p[1];
                l1 += p[2] + p[3];
                const int kc = j >> 1, hx = (j & 1) * 2;
                ph[kc][hx]     = packhl(p[0], p[1], pl[kc][hx]);
                ph[kc][hx + 1] = packhl(p[2], p[3], pl[kc][hx + 1]);
            }

            // ---- O += Ph*Vh + Ph*Vl + Pl*Vh ----
#pragma unroll
            for (int kc = 0; kc < 4; kc++)
#pragma unroll
                for (int jnp = 0; jnp < 4; jnp++) {
                    u32 vh[4], vl[4];
                    u32 row = (u32)(kc * 16 + ((lane >> 3) & 1) * 8 + (lane & 7));
                    u32 c16 = (u32)(jnp * 2 + (lane >> 4));
                    u32 off = row * 128 + ((c16 ^ (row & 7)) << 4);
                    ldsm4t(vh, vh_b + off);
                    ldsm4t(vl, vl_b + off);
                    const int jn0 = jnp * 2, jn1 = jn0 + 1;
                    mma16816(of[jn0], ph[kc], vh);
                    mma16816(of[jn0], ph[kc], vl);
                    mma16816(of[jn0], pl[kc], vh);
                    mma16816(of[jn1], ph[kc], vh + 2);
                    mma16816(of[jn1], ph[kc], vl + 2);
                    mma16816(of[jn1], pl[kc], vh + 2);
                }
        }

        // ---- epilogue: reduce l over the 4-lane group, normalize, store ----
        l0 += __shfl_xor_sync(0xffffffffu, l0, 1);
        l0 += __shfl_xor_sync(0xffffffffu, l0, 2);
        l1 += __shfl_xor_sync(0xffffffffu, l1, 1);
        l1 += __shfl_xor_sync(0xffffffffu, l1, 2);
        const float inv0 = 1.0f / l0, inv1 = 1.0f / l1;

        const size_t orow0 = (qr0 + g) * HD;
        const size_t orow1 = orow0 + 8 * HD;
#pragma unroll
        for (int jn = 0; jn < 8; jn++) {
            int col = jn * 8 + 2 * tig;
            *(float2*)&out[orow0 + col] =
                make_float2(of[jn][0] * inv0, of[jn][1] * inv0);
            *(float2*)&out[orow1 + col] =
                make_float2(of[jn][2] * inv1, of[jn][3] * inv1);
        }
    }
}

// ---------------------------------------------------------------------------
extern "C" void kernel_launch(void* const* d_in, const int* in_sizes, int n_in,
                              void* d_out, int out_size)
{
    const float* x  = (const float*)d_in[0];
    const float* Wq = (const float*)d_in[1];
    const float* Wk = (const float*)d_in[2];
    const float* Wv = (const float*)d_in[3];
    float* out = (float*)d_out;

    qkv_proj<<<(BATCH * SEQ) / 64, 256>>>(x, Wq, Wk, Wv);
    attn<<<dim3(32, BATCH), 128>>>(out);
}

// round 15
// speedup vs baseline: 3.5965x; 1.7028x over previous
#include <cuda_runtime.h>
#include <cuda_bf16.h>

#define BATCH 8
#define SEQ   4096
#define EMB   512
#define HD    64

typedef unsigned int u32;

// split operands (device globals, allocation-free). q/k/v row-major [t][h].
__device__ __nv_bfloat16 g_qh[BATCH * SEQ * HD];
__device__ __nv_bfloat16 g_ql[BATCH * SEQ * HD];
__device__ __nv_bfloat16 g_kh[BATCH * SEQ * HD];
__device__ __nv_bfloat16 g_vh[BATCH * SEQ * HD];
__device__ __nv_bfloat16 g_vl[BATCH * SEQ * HD];
__device__ __nv_bfloat16 g_wh[EMB * 192];   // [k][n], n = m*64+c
__device__ __nv_bfloat16 g_wl[EMB * 192];

// ---------------- helpers ----------------
__device__ __forceinline__ u32 s2u(const void* p) {
    u32 a;
    asm("{ .reg .u64 t; cvta.to.shared.u64 t, %1; cvt.u32.u64 %0, t; }"
        : "=r"(a) : "l"(p));
    return a;
}
__device__ __forceinline__ void ldsm4(u32* r, u32 addr) {
    asm volatile("ldmatrix.sync.aligned.m8n8.x4.shared.b16 {%0,%1,%2,%3}, [%4];"
        : "=r"(r[0]), "=r"(r[1]), "=r"(r[2]), "=r"(r[3]) : "r"(addr));
}
__device__ __forceinline__ void ldsm4t(u32* r, u32 addr) {
    asm volatile("ldmatrix.sync.aligned.m8n8.x4.trans.shared.b16 {%0,%1,%2,%3}, [%4];"
        : "=r"(r[0]), "=r"(r[1]), "=r"(r[2]), "=r"(r[3]) : "r"(addr));
}
__device__ __forceinline__ void mma16816(float* c, const u32* a, const u32* b) {
    asm volatile(
        "mma.sync.aligned.m16n8k16.row.col.f32.bf16.bf16.f32 "
        "{%0,%1,%2,%3}, {%4,%5,%6,%7}, {%8,%9}, {%0,%1,%2,%3};"
        : "+f"(c[0]), "+f"(c[1]), "+f"(c[2]), "+f"(c[3])
        : "r"(a[0]), "r"(a[1]), "r"(a[2]), "r"(a[3]), "r"(b[0]), "r"(b[1]));
}
__device__ __forceinline__ u32 packhl(float a, float b, u32& lo) {
    __nv_bfloat162 h = __floats2bfloat162_rn(a, b);
    __nv_bfloat162 l = __floats2bfloat162_rn(a - __bfloat162float(h.x),
                                             b - __bfloat162float(h.y));
    lo = *(u32*)&l;
    return *(u32*)&h;
}
__device__ __forceinline__ float ex2(float x) {
    float y; asm("ex2.approx.f32 %0, %1;" : "=f"(y) : "f"(x)); return y;
}
__device__ __forceinline__ void cpasync16(u32 dst, const void* src) {
    asm volatile("cp.async.cg.shared.global [%0], [%1], 16;"
                 :: "r"(dst), "l"(src) : "memory");
}
#define CP_COMMIT() asm volatile("cp.async.commit_group;" ::: "memory")
#define CP_WAIT0()  asm volatile("cp.async.wait_group 0;" ::: "memory")

// ---------------------------------------------------------------------------
// Pre-split weights to bf16 hi/lo: g_wh/g_wl[k][192], n = m*64+c.
// ---------------------------------------------------------------------------
__global__ void split_w(const float* __restrict__ Wq,
                        const float* __restrict__ Wk,
                        const float* __restrict__ Wv)
{
    int idx = blockIdx.x * 256 + threadIdx.x;   // < 98304
    int k = idx / 192, n = idx - k * 192;
    int m = n >> 6, c = n & 63;
    const float* w = (m == 0) ? Wq : ((m == 1) ? Wk : Wv);
    float v = w[k * HD + c];
    __nv_bfloat16 h = __float2bfloat16(v);
    g_wh[idx] = h;
    g_wl[idx] = __float2bfloat16(v - __bfloat162float(h));
}

// ---------------------------------------------------------------------------
// QKV projection on HMMA: x[32768,512] @ W[512,192], 3-pass bf16 split.
// CTA: 64 rows, 128 threads (4 warps, 16 rows each, all 192 cols).
// SMEM (64KB dyn): sXh@0, sXl@8K, W tiles @16K+sel*8K (sel 0-2 hi, 3-5 lo).
// ---------------------------------------------------------------------------
__global__ __launch_bounds__(128) void qkv_mma(const float* __restrict__ x)
{
    extern __shared__ __align__(16) char qs[];
    const u32 base = s2u(qs);
    const int tid = threadIdx.x;
    const int w = tid >> 5, lane = tid & 31;
    const int g = lane >> 2, tig = lane & 3;
    const long row0 = (long)blockIdx.x * 64;

    float of[3][8][4];
#pragma unroll
    for (int m = 0; m < 3; m++)
#pragma unroll
        for (int j = 0; j < 8; j++)
#pragma unroll
            for (int r = 0; r < 4; r++) of[m][j][r] = 0.f;

#pragma unroll 1
    for (int kb = 0; kb < EMB; kb += 64) {
        __syncthreads();
        // W tiles via cp.async (3072 16B groups)
#pragma unroll
        for (int l = 0; l < 24; l++) {
            int idx = tid + l * 128;
            int sel = idx >> 9, rem = idx & 511;
            int r = rem >> 3, c = rem & 7;
            int m = (sel >= 3) ? (sel - 3) : sel;
            const __nv_bfloat16* gp = (sel < 3) ? g_wh : g_wl;
            u32 d = base + 16384 + (u32)sel * 8192 +
                    (u32)r * 128 + (u32)((c ^ (r & 7)) << 4);
            cpasync16(d, gp + (size_t)(kb + r) * 192 + m * 64 + c * 8);
        }
        // x tile: load fp32, split, store swizzled bf16 hi/lo
#pragma unroll
        for (int l = 0; l < 4; l++) {
            int idx = tid + l * 128;
            int r = idx >> 3, c = idx & 7;
            const float* src = &x[(row0 + r) * EMB + kb + c * 8];
            float4 f0 = *(const float4*)src;
            float4 f1 = *(const float4*)(src + 4);
            u32 lo0, lo1, lo2, lo3;
            u32 h0 = packhl(f0.x, f0.y, lo0);
            u32 h1 = packhl(f0.z, f0.w, lo1);
            u32 h2 = packhl(f1.x, f1.y, lo2);
            u32 h3 = packhl(f1.z, f1.w, lo3);
            u32 d = (u32)r * 128 + (u32)((c ^ (r & 7)) << 4);
            *(uint4*)(qs + d)        = make_uint4(h0, h1, h2, h3);
            *(uint4*)(qs + 8192 + d) = make_uint4(lo0, lo1, lo2, lo3);
        }
        CP_COMMIT();
        CP_WAIT0();
        __syncthreads();

#pragma unroll
        for (int kc = 0; kc < 4; kc++) {
            u32 ah[4], al[4];
            {
                u32 row = (u32)(w * 16 + (lane & 15));
                u32 c16 = (u32)(kc * 2 + (lane >> 4));
                u32 off = row * 128 + ((c16 ^ (row & 7)) << 4);
                ldsm4(ah, base + off);
                ldsm4(al, base + 8192 + off);
            }
#pragma unroll
            for (int m = 0; m < 3; m++) {
                const u32 whb = base + 16384 + (u32)m * 8192;
                const u32 wlb = base + 16384 + (u32)(m + 3) * 8192;
#pragma unroll
                for (int jnp = 0; jnp < 4; jnp++) {
                    u32 bh[4], bl[4];
                    u32 row = (u32)(kc * 16 + ((lane >> 3) & 1) * 8 + (lane & 7));
                    u32 c16 = (u32)(jnp * 2 + (lane >> 4));
                    u32 off = row * 128 + ((c16 ^ (row & 7)) << 4);
                    ldsm4t(bh, whb + off);
                    ldsm4t(bl, wlb + off);
                    const int j0 = jnp * 2, j1 = j0 + 1;
                    mma16816(of[m][j0], ah, bh);
                    mma16816(of[m][j0], ah, bl);
                    mma16816(of[m][j0], al, bh);
                    mma16816(of[m][j1], ah, bh + 2);
                    mma16816(of[m][j1], ah, bl + 2);
                    mma16816(of[m][j1], al, bh + 2);
                }
            }
        }
    }

    // epilogue: split accumulators to hi/lo bf16 (kl not needed by attn)
    __nv_bfloat16* Hh[3] = {g_qh, g_kh, g_vh};
#pragma unroll
    for (int m = 0; m < 3; m++)
#pragma unroll
        for (int jf = 0; jf < 8; jf++) {
            long r0 = row0 + w * 16 + g;
            long r1 = r0 + 8;
            int col = jf * 8 + 2 * tig;
            u32 lo;
            u32 hi = packhl(of[m][jf][0], of[m][jf][1], lo);
            *(u32*)&Hh[m][r0 * HD + col] = hi;
            if (m == 0) *(u32*)&g_ql[r0 * HD + col] = lo;
            if (m == 2) *(u32*)&g_vl[r0 * HD + col] = lo;
            hi = packhl(of[m][jf][2], of[m][jf][3], lo);
            *(u32*)&Hh[m][r1 * HD + col] = hi;
            if (m == 0) *(u32*)&g_ql[r1 * HD + col] = lo;
            if (m == 2) *(u32*)&g_vl[r1 * HD + col] = lo;
        }
}

// ---------------------------------------------------------------------------
// Flash attention, HMMA: S = (Qh+Ql)*Kh (2-pass), PV = Ph*Vh+Ph*Vl+Pl*Vh.
// CTA: 256 thr (8 warps), Q-tile 128, K-tile 64, grid (16,8) = 128 CTAs,
// pair {bx, 31-bx} -> 66 k-tiles/CTA, 1 CTA/SM, double-buffered cp.async.
// SMEM 48KB: buf(i) @ i*24K: Kh@0, Vh@8K, Vl@16K, SW128-swizzled.
// ---------------------------------------------------------------------------
__global__ __launch_bounds__(256) void attn(float* __restrict__ out)
{
    extern __shared__ __align__(16) char sm[];
    const u32 smb = s2u(sm);
    const int tid = threadIdx.x;
    const int w = tid >> 5, lane = tid & 31;
    const int g = lane >> 2, tig = lane & 3;
    const int b = blockIdx.y, bx = blockIdx.x;
    const float cfac = 0.06375871655f;   // 512^-0.5 * log2(e)

#pragma unroll 1
    for (int half = 0; half < 2; half++) {
        const int qi = half ? (31 - bx) : bx;
        const int nkt = 2 * qi + 2;
        const size_t qr0 = (size_t)b * SEQ + (size_t)qi * 128 + w * 16;
        const int w0 = qi * 128 + w * 16;

        // Q A-frags from gmem (held in regs for the whole half)
        u32 qh[4][4], ql[4][4];
#pragma unroll
        for (int kc = 0; kc < 4; kc++)
#pragma unroll
            for (int rr = 0; rr < 4; rr++) {
                size_t row = qr0 + g + (rr & 1) * 8;
                int col = kc * 16 + (rr >> 1) * 8 + 2 * tig;
                qh[kc][rr] = *(const u32*)&g_qh[row * HD + col];
                ql[kc][rr] = *(const u32*)&g_ql[row * HD + col];
            }

        float of[8][4];
#pragma unroll
        for (int jn = 0; jn < 8; jn++)
#pragma unroll
            for (int r = 0; r < 4; r++) of[jn][r] = 0.f;
        float l0 = 0.f, l1 = 0.f;

        __syncthreads();   // prior half done with smem
        // preload tile 0 -> buf 0
        {
            const size_t kb0 = (size_t)b * SEQ;
#pragma unroll
            for (int l = 0; l < 6; l++) {
                int idx = tid + l * 256;
                int arr = idx >> 9, rem = idx & 511;
                int r = rem >> 3, c = rem & 7;
                u32 d = smb + (u32)arr * 8192 + (u32)r * 128 +
                        (u32)((c ^ (r & 7)) << 4);
                const __nv_bfloat16* gp =
                    (arr == 0) ? g_kh : ((arr == 1) ? g_vh : g_vl);
                cpasync16(d, gp + (kb0 + r) * HD + c * 8);
            }
            CP_COMMIT();
        }

#pragma unroll 1
        for (int kt = 0; kt < nkt; kt++) {
            CP_WAIT0();
            __syncthreads();
            const u32 buf = smb + (u32)(kt & 1) * 24576;
            if (kt + 1 < nkt) {      // prefetch next tile into other buffer
                const size_t kbn = (size_t)b * SEQ + (size_t)(kt + 1) * 64;
                const u32 nb = smb + (u32)((kt + 1) & 1) * 24576;
#pragma unroll
                for (int l = 0; l < 6; l++) {
                    int idx = tid + l * 256;
                    int arr = idx >> 9, rem = idx & 511;
                    int r = rem >> 3, c = rem & 7;
                    u32 d = nb + (u32)arr * 8192 + (u32)r * 128 +
                            (u32)((c ^ (r & 7)) << 4);
                    const __nv_bfloat16* gp =
                        (arr == 0) ? g_kh : ((arr == 1) ? g_vh : g_vl);
                    cpasync16(d, gp + (kbn + r) * HD + c * 8);
                }
                CP_COMMIT();
            }

            if (kt * 64 > w0 + 15) continue;   // warp fully above diagonal
            const bool dg = (kt * 64 + 63 > w0);

            u32 ph[4][4], pl[4][4];
            // ---- S = (Qh + Ql) * Kh ; softmax (no max needed) ; pack P ----
#pragma unroll
            for (int j = 0; j < 8; j++) {
                float s[4] = {0.f, 0.f, 0.f, 0.f};
                u32 bh[8];
                {
                    u32 row = (u32)(j * 8 + (lane & 7));
                    u32 c16 = (u32)(lane >> 3);
                    ldsm4(bh, buf + row * 128 + ((c16 ^ (row & 7)) << 4));
                    ldsm4(bh + 4, buf + row * 128 + (((c16 + 4) ^ (row & 7)) << 4));
                }
#pragma unroll
                for (int kc = 0; kc < 4; kc++) {
                    mma16816(s, qh[kc], bh + 2 * kc);
                    mma16816(s, ql[kc], bh + 2 * kc);
                }
                float p[4];
#pragma unroll
                for (int r = 0; r < 4; r++) {
                    float pv = ex2(s[r] * cfac);
                    if (dg) {
                        int key = kt * 64 + j * 8 + 2 * tig + (r & 1);
                        int qrl = w0 + g + ((r >> 1) << 3);
                        if (key > qrl) pv = 0.f;
                    }
                    p[r] = pv;
                }
                l0 += p[0] + p[1];
                l1 += p[2] + p[3];
                const int kc = j >> 1, hx = (j & 1) * 2;
                ph[kc][hx]     = packhl(p[0], p[1], pl[kc][hx]);
                ph[kc][hx + 1] = packhl(p[2], p[3], pl[kc][hx + 1]);
            }

            // ---- O += Ph*Vh + Ph*Vl + Pl*Vh ----
            const u32 vhb = buf + 8192, vlb = buf + 16384;
#pragma unroll
            for (int kc = 0; kc < 4; kc++)
#pragma unroll
                for (int jnp = 0; jnp < 4; jnp++) {
                    u32 vh[4], vl[4];
                    u32 row = (u32)(kc * 16 + ((lane >> 3) & 1) * 8 + (lane & 7));
                    u32 c16 = (u32)(jnp * 2 + (lane >> 4));
                    u32 off = row * 128 + ((c16 ^ (row & 7)) << 4);
                    ldsm4t(vh, vhb + off);
                    ldsm4t(vl, vlb + off);
                    const int jn0 = jnp * 2, jn1 = jn0 + 1;
                    mma16816(of[jn0], ph[kc], vh);
                    mma16816(of[jn0], ph[kc], vl);
                    mma16816(of[jn0], pl[kc], vh);
                    mma16816(of[jn1], ph[kc], vh + 2);
                    mma16816(of[jn1], ph[kc], vl + 2);
                    mma16816(of[jn1], pl[kc], vh + 2);
                }
        }

        // ---- epilogue ----
        l0 += __shfl_xor_sync(0xffffffffu, l0, 1);
        l0 += __shfl_xor_sync(0xffffffffu, l0, 2);
        l1 += __shfl_xor_sync(0xffffffffu, l1, 1);
        l1 += __shfl_xor_sync(0xffffffffu, l1, 2);
        const float inv0 = 1.0f / l0, inv1 = 1.0f / l1;

        const size_t orow0 = (qr0 + g) * HD;
        const size_t orow1 = orow0 + 8 * HD;
#pragma unroll
        for (int jn = 0; jn < 8; jn++) {
            int col = jn * 8 + 2 * tig;
            *(float2*)&out[orow0 + col] =
                make_float2(of[jn][0] * inv0, of[jn][1] * inv0);
            *(float2*)&out[orow1 + col] =
                make_float2(of[jn][2] * inv1, of[jn][3] * inv1);
        }
    }
}

// ---------------------------------------------------------------------------
extern "C" void kernel_launch(void* const* d_in, const int* in_sizes, int n_in,
                              void* d_out, int out_size)
{
    const float* x  = (const float*)d_in[0];
    const float* Wq = (const float*)d_in[1];
    const float* Wk = (const float*)d_in[2];
    const float* Wv = (const float*)d_in[3];
    float* out = (float*)d_out;

    cudaFuncSetAttribute(qkv_mma, cudaFuncAttributeMaxDynamicSharedMemorySize,
                         65536);
    cudaFuncSetAttribute(attn, cudaFuncAttributeMaxDynamicSharedMemorySize,
                         49152);

    split_w<<<384, 256>>>(Wq, Wk, Wv);
    qkv_mma<<<(BATCH * SEQ) / 64, 128, 65536>>>(x);
    attn<<<dim3(16, BATCH), 256, 49152>>>(out);
}

// round 16
// speedup vs baseline: 4.8741x; 1.3552x over previous
#include <cuda_runtime.h>
#include <cuda_bf16.h>
#include <cuda_fp16.h>

#define BATCH 8
#define SEQ   4096
#define EMB   512
#define HD    64

typedef unsigned int u32;

// operands (device globals, allocation-free). row-major [t][h].
__device__ __half g_q16[BATCH * SEQ * HD];
__device__ __half g_k16[BATCH * SEQ * HD];
__device__ __half g_v16h[BATCH * SEQ * HD];
__device__ __half g_v16l[BATCH * SEQ * HD];
__device__ __nv_bfloat16 g_wh[EMB * 192];   // [k][n], n = m*64+c
__device__ __nv_bfloat16 g_wl[EMB * 192];

// ---------------- helpers ----------------
__device__ __forceinline__ u32 s2u(const void* p) {
    u32 a;
    asm("{ .reg .u64 t; cvta.to.shared.u64 t, %1; cvt.u32.u64 %0, t; }"
        : "=r"(a) : "l"(p));
    return a;
}
__device__ __forceinline__ void ldsm4(u32* r, u32 addr) {
    asm volatile("ldmatrix.sync.aligned.m8n8.x4.shared.b16 {%0,%1,%2,%3}, [%4];"
        : "=r"(r[0]), "=r"(r[1]), "=r"(r[2]), "=r"(r[3]) : "r"(addr));
}
__device__ __forceinline__ void ldsm4t(u32* r, u32 addr) {
    asm volatile("ldmatrix.sync.aligned.m8n8.x4.trans.shared.b16 {%0,%1,%2,%3}, [%4];"
        : "=r"(r[0]), "=r"(r[1]), "=r"(r[2]), "=r"(r[3]) : "r"(addr));
}
__device__ __forceinline__ void mma_bf16(float* c, const u32* a, const u32* b) {
    asm volatile(
        "mma.sync.aligned.m16n8k16.row.col.f32.bf16.bf16.f32 "
        "{%0,%1,%2,%3}, {%4,%5,%6,%7}, {%8,%9}, {%0,%1,%2,%3};"
        : "+f"(c[0]), "+f"(c[1]), "+f"(c[2]), "+f"(c[3])
        : "r"(a[0]), "r"(a[1]), "r"(a[2]), "r"(a[3]), "r"(b[0]), "r"(b[1]));
}
__device__ __forceinline__ void mma_f16(float* c, const u32* a, const u32* b) {
    asm volatile(
        "mma.sync.aligned.m16n8k16.row.col.f32.f16.f16.f32 "
        "{%0,%1,%2,%3}, {%4,%5,%6,%7}, {%8,%9}, {%0,%1,%2,%3};"
        : "+f"(c[0]), "+f"(c[1]), "+f"(c[2]), "+f"(c[3])
        : "r"(a[0]), "r"(a[1]), "r"(a[2]), "r"(a[3]), "r"(b[0]), "r"(b[1]));
}
// bf16 hi/lo pack (for qkv internals)
__device__ __forceinline__ u32 packhl_bf(float a, float b, u32& lo) {
    __nv_bfloat162 h = __floats2bfloat162_rn(a, b);
    __nv_bfloat162 l = __floats2bfloat162_rn(a - __bfloat162float(h.x),
                                             b - __bfloat162float(h.y));
    lo = *(u32*)&l;
    return *(u32*)&h;
}
// fp16 pack (hi only) and hi/lo pack
__device__ __forceinline__ u32 packh16(float a, float b) {
    __half2 h = __floats2half2_rn(a, b);
    return *(u32*)&h;
}
__device__ __forceinline__ u32 packhl16(float a, float b, u32& lo) {
    __half2 h = __floats2half2_rn(a, b);
    __half2 l = __floats2half2_rn(a - __half2float(h.x),
                                  b - __half2float(h.y));
    lo = *(u32*)&l;
    return *(u32*)&h;
}
__device__ __forceinline__ float ex2(float x) {
    float y; asm("ex2.approx.f32 %0, %1;" : "=f"(y) : "f"(x)); return y;
}
__device__ __forceinline__ void cpasync16(u32 dst, const void* src) {
    asm volatile("cp.async.cg.shared.global [%0], [%1], 16;"
                 :: "r"(dst), "l"(src) : "memory");
}
#define CP_COMMIT() asm volatile("cp.async.commit_group;" ::: "memory")
#define CP_WAIT0()  asm volatile("cp.async.wait_group 0;" ::: "memory")

// ---------------------------------------------------------------------------
// Pre-split weights to bf16 hi/lo: g_wh/g_wl[k][192], n = m*64+c.
// ---------------------------------------------------------------------------
__global__ void split_w(const float* __restrict__ Wq,
                        const float* __restrict__ Wk,
                        const float* __restrict__ Wv)
{
    int idx = blockIdx.x * 256 + threadIdx.x;   // < 98304
    int k = idx / 192, n = idx - k * 192;
    int m = n >> 6, c = n & 63;
    const float* w = (m == 0) ? Wq : ((m == 1) ? Wk : Wv);
    float v = w[k * HD + c];
    __nv_bfloat16 h = __float2bfloat16(v);
    g_wh[idx] = h;
    g_wl[idx] = __float2bfloat16(v - __bfloat162float(h));
}

// ---------------------------------------------------------------------------
// QKV projection on HMMA: x[32768,512] @ W[512,192], 3-pass bf16 split.
// CTA: 64 rows, 128 threads. Epilogue emits fp16 q/k and fp16 hi/lo v.
// SMEM (64KB dyn): sXh@0, sXl@8K, W tiles @16K+sel*8K (sel 0-2 hi, 3-5 lo).
// ---------------------------------------------------------------------------
__global__ __launch_bounds__(128) void qkv_mma(const float* __restrict__ x)
{
    extern __shared__ __align__(16) char qs[];
    const u32 base = s2u(qs);
    const int tid = threadIdx.x;
    const int w = tid >> 5, lane = tid & 31;
    const int g = lane >> 2, tig = lane & 3;
    const long row0 = (long)blockIdx.x * 64;

    float of[3][8][4];
#pragma unroll
    for (int m = 0; m < 3; m++)
#pragma unroll
        for (int j = 0; j < 8; j++)
#pragma unroll
            for (int r = 0; r < 4; r++) of[m][j][r] = 0.f;

#pragma unroll 1
    for (int kb = 0; kb < EMB; kb += 64) {
        __syncthreads();
#pragma unroll
        for (int l = 0; l < 24; l++) {
            int idx = tid + l * 128;
            int sel = idx >> 9, rem = idx & 511;
            int r = rem >> 3, c = rem & 7;
            int m = (sel >= 3) ? (sel - 3) : sel;
            const __nv_bfloat16* gp = (sel < 3) ? g_wh : g_wl;
            u32 d = base + 16384 + (u32)sel * 8192 +
                    (u32)r * 128 + (u32)((c ^ (r & 7)) << 4);
            cpasync16(d, gp + (size_t)(kb + r) * 192 + m * 64 + c * 8);
        }
#pragma unroll
        for (int l = 0; l < 4; l++) {
            int idx = tid + l * 128;
            int r = idx >> 3, c = idx & 7;
            const float* src = &x[(row0 + r) * EMB + kb + c * 8];
            float4 f0 = *(const float4*)src;
            float4 f1 = *(const float4*)(src + 4);
            u32 lo0, lo1, lo2, lo3;
            u32 h0 = packhl_bf(f0.x, f0.y, lo0);
            u32 h1 = packhl_bf(f0.z, f0.w, lo1);
            u32 h2 = packhl_bf(f1.x, f1.y, lo2);
            u32 h3 = packhl_bf(f1.z, f1.w, lo3);
            u32 d = (u32)r * 128 + (u32)((c ^ (r & 7)) << 4);
            *(uint4*)(qs + d)        = make_uint4(h0, h1, h2, h3);
            *(uint4*)(qs + 8192 + d) = make_uint4(lo0, lo1, lo2, lo3);
        }
        CP_COMMIT();
        CP_WAIT0();
        __syncthreads();

#pragma unroll
        for (int kc = 0; kc < 4; kc++) {
            u32 ah[4], al[4];
            {
                u32 row = (u32)(w * 16 + (lane & 15));
                u32 c16 = (u32)(kc * 2 + (lane >> 4));
                u32 off = row * 128 + ((c16 ^ (row & 7)) << 4);
                ldsm4(ah, base + off);
                ldsm4(al, base + 8192 + off);
            }
#pragma unroll
            for (int m = 0; m < 3; m++) {
                const u32 whb = base + 16384 + (u32)m * 8192;
                const u32 wlb = base + 16384 + (u32)(m + 3) * 8192;
#pragma unroll
                for (int jnp = 0; jnp < 4; jnp++) {
                    u32 bh[4], bl[4];
                    u32 row = (u32)(kc * 16 + ((lane >> 3) & 1) * 8 + (lane & 7));
                    u32 c16 = (u32)(jnp * 2 + (lane >> 4));
                    u32 off = row * 128 + ((c16 ^ (row & 7)) << 4);
                    ldsm4t(bh, whb + off);
                    ldsm4t(bl, wlb + off);
                    const int j0 = jnp * 2, j1 = j0 + 1;
                    mma_bf16(of[m][j0], ah, bh);
                    mma_bf16(of[m][j0], ah, bl);
                    mma_bf16(of[m][j0], al, bh);
                    mma_bf16(of[m][j1], ah, bh + 2);
                    mma_bf16(of[m][j1], ah, bl + 2);
                    mma_bf16(of[m][j1], al, bh + 2);
                }
            }
        }
    }

    // epilogue: fp16 outputs (q, k single; v hi/lo)
#pragma unroll
    for (int jf = 0; jf < 8; jf++) {
        long r0 = row0 + w * 16 + g;
        long r1 = r0 + 8;
        int col = jf * 8 + 2 * tig;
        *(u32*)&g_q16[r0 * HD + col] = packh16(of[0][jf][0], of[0][jf][1]);
        *(u32*)&g_q16[r1 * HD + col] = packh16(of[0][jf][2], of[0][jf][3]);
        *(u32*)&g_k16[r0 * HD + col] = packh16(of[1][jf][0], of[1][jf][1]);
        *(u32*)&g_k16[r1 * HD + col] = packh16(of[1][jf][2], of[1][jf][3]);
        u32 lo;
        u32 hi = packhl16(of[2][jf][0], of[2][jf][1], lo);
        *(u32*)&g_v16h[r0 * HD + col] = hi;
        *(u32*)&g_v16l[r0 * HD + col] = lo;
        hi = packhl16(of[2][jf][2], of[2][jf][3], lo);
        *(u32*)&g_v16h[r1 * HD + col] = hi;
        *(u32*)&g_v16l[r1 * HD + col] = lo;
    }
}

// ---------------------------------------------------------------------------
// Flash attention, fp16 HMMA: S = q16*K16 (1 pass), PV = P16*(Vh+Vl) (2).
// CTA: 128 thr (4 warps), Q-tile 64, K-tile 64, grid (32,8) = 256 CTAs
// -> 2 CTAs/SM. Pair {bx, 63-bx} -> 65 k-tiles/CTA. Double-buffered cp.async.
// SMEM 48KB: buf(i) @ i*24K: K16@0, Vh@8K, Vl@16K, SW128-swizzled.
// ---------------------------------------------------------------------------
__global__ __launch_bounds__(128, 2) void attn(float* __restrict__ out)
{
    extern __shared__ __align__(16) char sm[];
    const u32 smb = s2u(sm);
    const int tid = threadIdx.x;
    const int w = tid >> 5, lane = tid & 31;
    const int g = lane >> 2, tig = lane & 3;
    const int b = blockIdx.y, bx = blockIdx.x;
    const float cfac = 0.06375871655f;   // 512^-0.5 * log2(e)

#pragma unroll 1
    for (int half = 0; half < 2; half++) {
        const int qi = half ? (63 - bx) : bx;
        const int nkt = qi + 1;
        const size_t qr0 = (size_t)b * SEQ + (size_t)qi * 64 + w * 16;
        const int w0 = qi * 64 + w * 16;

        // Q A-frags (fp16) from gmem, held in regs for the whole half
        u32 q16[4][4];
#pragma unroll
        for (int kc = 0; kc < 4; kc++)
#pragma unroll
            for (int rr = 0; rr < 4; rr++) {
                size_t row = qr0 + g + (rr & 1) * 8;
                int col = kc * 16 + (rr >> 1) * 8 + 2 * tig;
                q16[kc][rr] = *(const u32*)&g_q16[row * HD + col];
            }

        float of[8][4];
#pragma unroll
        for (int jn = 0; jn < 8; jn++)
#pragma unroll
            for (int r = 0; r < 4; r++) of[jn][r] = 0.f;
        float l0 = 0.f, l1 = 0.f;

        __syncthreads();   // prior half done with smem
        {
            const size_t kb0 = (size_t)b * SEQ;
#pragma unroll
            for (int l = 0; l < 12; l++) {
                int idx = tid + l * 128;
                int arr = idx >> 9, rem = idx & 511;
                int r = rem >> 3, c = rem & 7;
                u32 d = smb + (u32)arr * 8192 + (u32)r * 128 +
                        (u32)((c ^ (r & 7)) << 4);
                const __half* gp =
                    (arr == 0) ? g_k16 : ((arr == 1) ? g_v16h : g_v16l);
                cpasync16(d, gp + (kb0 + r) * HD + c * 8);
            }
            CP_COMMIT();
        }

#pragma unroll 1
        for (int kt = 0; kt < nkt; kt++) {
            CP_WAIT0();
            __syncthreads();
            const u32 buf = smb + (u32)(kt & 1) * 24576;
            if (kt + 1 < nkt) {
                const size_t kbn = (size_t)b * SEQ + (size_t)(kt + 1) * 64;
                const u32 nb = smb + (u32)((kt + 1) & 1) * 24576;
#pragma unroll
                for (int l = 0; l < 12; l++) {
                    int idx = tid + l * 128;
                    int arr = idx >> 9, rem = idx & 511;
                    int r = rem >> 3, c = rem & 7;
                    u32 d = nb + (u32)arr * 8192 + (u32)r * 128 +
                            (u32)((c ^ (r & 7)) << 4);
                    const __half* gp =
                        (arr == 0) ? g_k16 : ((arr == 1) ? g_v16h : g_v16l);
                    cpasync16(d, gp + (kbn + r) * HD + c * 8);
                }
                CP_COMMIT();
            }

            if (kt * 64 > w0 + 15) continue;   // warp fully above diagonal
            const bool dg = (kt * 64 + 63 > w0);

            u32 p16[4][4];
            // ---- S = q16 * K16 (single pass) ; softmax ; pack P (hi only) ----
#pragma unroll
            for (int j = 0; j < 8; j++) {
                float s[4] = {0.f, 0.f, 0.f, 0.f};
                u32 bh[8];
                {
                    u32 row = (u32)(j * 8 + (lane & 7));
                    u32 c16 = (u32)(lane >> 3);
                    ldsm4(bh, buf + row * 128 + ((c16 ^ (row & 7)) << 4));
                    ldsm4(bh + 4, buf + row * 128 + (((c16 + 4) ^ (row & 7)) << 4));
                }
#pragma unroll
                for (int kc = 0; kc < 4; kc++)
                    mma_f16(s, q16[kc], bh + 2 * kc);
                float p[4];
#pragma unroll
                for (int r = 0; r < 4; r++) {
                    float pv = ex2(s[r] * cfac);
                    if (dg) {
                        int key = kt * 64 + j * 8 + 2 * tig + (r & 1);
                        int qrl = w0 + g + ((r >> 1) << 3);
                        if (key > qrl) pv = 0.f;
                    }
                    p[r] = pv;
                }
                l0 += p[0] + p[1];
                l1 += p[2] + p[3];
                const int kc = j >> 1, hx = (j & 1) * 2;
                p16[kc][hx]     = packh16(p[0], p[1]);
                p16[kc][hx + 1] = packh16(p[2], p[3]);
            }

            // ---- O += P16*Vh + P16*Vl ----
            const u32 vhb = buf + 8192, vlb = buf + 16384;
#pragma unroll
            for (int kc = 0; kc < 4; kc++)
#pragma unroll
                for (int jnp = 0; jnp < 4; jnp++) {
                    u32 vh[4], vl[4];
                    u32 row = (u32)(kc * 16 + ((lane >> 3) & 1) * 8 + (lane & 7));
                    u32 c16 = (u32)(jnp * 2 + (lane >> 4));
                    u32 off = row * 128 + ((c16 ^ (row & 7)) << 4);
                    ldsm4t(vh, vhb + off);
                    ldsm4t(vl, vlb + off);
                    const int jn0 = jnp * 2, jn1 = jn0 + 1;
                    mma_f16(of[jn0], p16[kc], vh);
                    mma_f16(of[jn0], p16[kc], vl);
                    mma_f16(of[jn1], p16[kc], vh + 2);
                    mma_f16(of[jn1], p16[kc], vl + 2);
                }
        }

        // ---- epilogue ----
        l0 += __shfl_xor_sync(0xffffffffu, l0, 1);
        l0 += __shfl_xor_sync(0xffffffffu, l0, 2);
        l1 += __shfl_xor_sync(0xffffffffu, l1, 1);
        l1 += __shfl_xor_sync(0xffffffffu, l1, 2);
        const float inv0 = 1.0f / l0, inv1 = 1.0f / l1;

        const size_t orow0 = (qr0 + g) * HD;
        const size_t orow1 = orow0 + 8 * HD;
#pragma unroll
        for (int jn = 0; jn < 8; jn++) {
            int col = jn * 8 + 2 * tig;
            *(float2*)&out[orow0 + col] =
                make_float2(of[jn][0] * inv0, of[jn][1] * inv0);
            *(float2*)&out[orow1 + col] =
                make_float2(of[jn][2] * inv1, of[jn][3] * inv1);
        }
    }
}

// ---------------------------------------------------------------------------
extern "C" void kernel_launch(void* const* d_in, const int* in_sizes, int n_in,
                              void* d_out, int out_size)
{
    const float* x  = (const float*)d_in[0];
    const float* Wq = (const float*)d_in[1];
    const float* Wk = (const float*)d_in[2];
    const float* Wv = (const float*)d_in[3];
    float* out = (float*)d_out;

    cudaFuncSetAttribute(qkv_mma, cudaFuncAttributeMaxDynamicSharedMemorySize,
                         65536);
    cudaFuncSetAttribute(attn, cudaFuncAttributeMaxDynamicSharedMemorySize,
                         49152);

    split_w<<<384, 256>>>(Wq, Wk, Wv);
    qkv_mma<<<(BATCH * SEQ) / 64, 128, 65536>>>(x);
    attn<<<dim3(32, BATCH), 128, 49152>>>(out);
}

// round 17
// speedup vs baseline: 5.9434x; 1.2194x over previous
#include <cuda_runtime.h>
#include <cuda_fp16.h>

#define BATCH 8
#define SEQ   4096
#define EMB   512
#define HD    64

typedef unsigned int u32;

// operands (device globals, allocation-free). row-major [t][h].
__device__ __half g_q16[BATCH * SEQ * HD];
__device__ __half g_k16[BATCH * SEQ * HD];
__device__ __half g_v16[BATCH * SEQ * HD];
__device__ __half g_w16[EMB * 192];   // [k][n], n = m*64+c

// ---------------- helpers ----------------
__device__ __forceinline__ u32 s2u(const void* p) {
    u32 a;
    asm("{ .reg .u64 t; cvta.to.shared.u64 t, %1; cvt.u32.u64 %0, t; }"
        : "=r"(a) : "l"(p));
    return a;
}
__device__ __forceinline__ void ldsm4(u32* r, u32 addr) {
    asm volatile("ldmatrix.sync.aligned.m8n8.x4.shared.b16 {%0,%1,%2,%3}, [%4];"
        : "=r"(r[0]), "=r"(r[1]), "=r"(r[2]), "=r"(r[3]) : "r"(addr));
}
__device__ __forceinline__ void ldsm4t(u32* r, u32 addr) {
    asm volatile("ldmatrix.sync.aligned.m8n8.x4.trans.shared.b16 {%0,%1,%2,%3}, [%4];"
        : "=r"(r[0]), "=r"(r[1]), "=r"(r[2]), "=r"(r[3]) : "r"(addr));
}
__device__ __forceinline__ void mma_f16(float* c, const u32* a, const u32* b) {
    asm volatile(
        "mma.sync.aligned.m16n8k16.row.col.f32.f16.f16.f32 "
        "{%0,%1,%2,%3}, {%4,%5,%6,%7}, {%8,%9}, {%0,%1,%2,%3};"
        : "+f"(c[0]), "+f"(c[1]), "+f"(c[2]), "+f"(c[3])
        : "r"(a[0]), "r"(a[1]), "r"(a[2]), "r"(a[3]), "r"(b[0]), "r"(b[1]));
}
__device__ __forceinline__ u32 packh16(float a, float b) {
    __half2 h = __floats2half2_rn(a, b);
    return *(u32*)&h;
}
__device__ __forceinline__ u32 packhl16(float a, float b, u32& lo) {
    __half2 h = __floats2half2_rn(a, b);
    __half2 l = __floats2half2_rn(a - __half2float(h.x),
                                  b - __half2float(h.y));
    lo = *(u32*)&l;
    return *(u32*)&h;
}
__device__ __forceinline__ float ex2(float x) {
    float y; asm("ex2.approx.f32 %0, %1;" : "=f"(y) : "f"(x)); return y;
}
__device__ __forceinline__ void cpasync16(u32 dst, const void* src) {
    asm volatile("cp.async.cg.shared.global [%0], [%1], 16;"
                 :: "r"(dst), "l"(src) : "memory");
}
#define CP_COMMIT() asm volatile("cp.async.commit_group;" ::: "memory")
#define CP_WAIT0()  asm volatile("cp.async.wait_group 0;" ::: "memory")

// ---------------------------------------------------------------------------
// Convert weights to fp16: g_w16[k][192], n = m*64+c.
// ---------------------------------------------------------------------------
__global__ void split_w(const float* __restrict__ Wq,
                        const float* __restrict__ Wk,
                        const float* __restrict__ Wv)
{
    int idx = blockIdx.x * 256 + threadIdx.x;   // < 98304
    int k = idx / 192, n = idx - k * 192;
    int m = n >> 6, c = n & 63;
    const float* w = (m == 0) ? Wq : ((m == 1) ? Wk : Wv);
    g_w16[idx] = __float2half(w[k * HD + c]);
}

// ---------------------------------------------------------------------------
// QKV projection on fp16 HMMA: out = (xh + xl) * w16 (2-pass x-split).
// CTA: 64 rows, 128 threads (4 warps, 16 rows each, all 192 cols).
// SMEM (40KB dyn): sXh@0, sXl@8K, W tiles @16K + m*8K.
// ---------------------------------------------------------------------------
__global__ __launch_bounds__(128) void qkv_mma(const float* __restrict__ x)
{
    extern __shared__ __align__(16) char qs[];
    const u32 base = s2u(qs);
    const int tid = threadIdx.x;
    const int w = tid >> 5, lane = tid & 31;
    const int g = lane >> 2, tig = lane & 3;
    const long row0 = (long)blockIdx.x * 64;

    float of[3][8][4];
#pragma unroll
    for (int m = 0; m < 3; m++)
#pragma unroll
        for (int j = 0; j < 8; j++)
#pragma unroll
            for (int r = 0; r < 4; r++) of[m][j][r] = 0.f;

#pragma unroll 1
    for (int kb = 0; kb < EMB; kb += 64) {
        __syncthreads();
        // W tiles via cp.async: 3 matrices x 64x64 fp16 (1536 16B groups)
#pragma unroll
        for (int l = 0; l < 12; l++) {
            int idx = tid + l * 128;
            int m = idx >> 9, rem = idx & 511;
            int r = rem >> 3, c = rem & 7;
            u32 d = base + 16384 + (u32)m * 8192 +
                    (u32)r * 128 + (u32)((c ^ (r & 7)) << 4);
            cpasync16(d, g_w16 + (size_t)(kb + r) * 192 + m * 64 + c * 8);
        }
        // x tile: load fp32, split to fp16 hi/lo, store swizzled
#pragma unroll
        for (int l = 0; l < 4; l++) {
            int idx = tid + l * 128;
            int r = idx >> 3, c = idx & 7;
            const float* src = &x[(row0 + r) * EMB + kb + c * 8];
            float4 f0 = *(const float4*)src;
            float4 f1 = *(const float4*)(src + 4);
            u32 lo0, lo1, lo2, lo3;
            u32 h0 = packhl16(f0.x, f0.y, lo0);
            u32 h1 = packhl16(f0.z, f0.w, lo1);
            u32 h2 = packhl16(f1.x, f1.y, lo2);
            u32 h3 = packhl16(f1.z, f1.w, lo3);
            u32 d = (u32)r * 128 + (u32)((c ^ (r & 7)) << 4);
            *(uint4*)(qs + d)        = make_uint4(h0, h1, h2, h3);
            *(uint4*)(qs + 8192 + d) = make_uint4(lo0, lo1, lo2, lo3);
        }
        CP_COMMIT();
        CP_WAIT0();
        __syncthreads();

#pragma unroll
        for (int kc = 0; kc < 4; kc++) {
            u32 ah[4], al[4];
            {
                u32 row = (u32)(w * 16 + (lane & 15));
                u32 c16 = (u32)(kc * 2 + (lane >> 4));
                u32 off = row * 128 + ((c16 ^ (row & 7)) << 4);
                ldsm4(ah, base + off);
                ldsm4(al, base + 8192 + off);
            }
#pragma unroll
            for (int m = 0; m < 3; m++) {
                const u32 wb = base + 16384 + (u32)m * 8192;
#pragma unroll
                for (int jnp = 0; jnp < 4; jnp++) {
                    u32 bh[4];
                    u32 row = (u32)(kc * 16 + ((lane >> 3) & 1) * 8 + (lane & 7));
                    u32 c16 = (u32)(jnp * 2 + (lane >> 4));
                    u32 off = row * 128 + ((c16 ^ (row & 7)) << 4);
                    ldsm4t(bh, wb + off);
                    const int j0 = jnp * 2, j1 = j0 + 1;
                    mma_f16(of[m][j0], ah, bh);
                    mma_f16(of[m][j0], al, bh);
                    mma_f16(of[m][j1], ah, bh + 2);
                    mma_f16(of[m][j1], al, bh + 2);
                }
            }
        }
    }

    // epilogue: fp16 outputs
    __half* dst[3] = {g_q16, g_k16, g_v16};
#pragma unroll
    for (int m = 0; m < 3; m++)
#pragma unroll
        for (int jf = 0; jf < 8; jf++) {
            long r0 = row0 + w * 16 + g;
            long r1 = r0 + 8;
            int col = jf * 8 + 2 * tig;
            *(u32*)&dst[m][r0 * HD + col] = packh16(of[m][jf][0], of[m][jf][1]);
            *(u32*)&dst[m][r1 * HD + col] = packh16(of[m][jf][2], of[m][jf][3]);
        }
}

// ---------------------------------------------------------------------------
// Flash attention, fp16 HMMA: S = q16*K16 (1 pass), PV = P16*V16 (1 pass).
// CTA: 128 thr (4 warps), Q-tile 64, K-tile 64, grid (32,8) = 256 CTAs
// -> 2 CTAs/SM, one wave. Pair {bx, 63-bx} -> 65 k-tiles/CTA.
// SMEM 32KB: buf(i) @ i*16K: K16@0, V16@8K, SW128-swizzled.
// ---------------------------------------------------------------------------
__global__ __launch_bounds__(128, 2) void attn(float* __restrict__ out)
{
    extern __shared__ __align__(16) char sm[];
    const u32 smb = s2u(sm);
    const int tid = threadIdx.x;
    const int w = tid >> 5, lane = tid & 31;
    const int g = lane >> 2, tig = lane & 3;
    const int b = blockIdx.y, bx = blockIdx.x;
    const float cfac = 0.06375871655f;   // 512^-0.5 * log2(e)

#pragma unroll 1
    for (int half = 0; half < 2; half++) {
        const int qi = half ? (63 - bx) : bx;
        const int nkt = qi + 1;
        const size_t qr0 = (size_t)b * SEQ + (size_t)qi * 64 + w * 16;
        const int w0 = qi * 64 + w * 16;

        // Q A-frags (fp16) from gmem, held in regs for the whole half
        u32 q16[4][4];
#pragma unroll
        for (int kc = 0; kc < 4; kc++)
#pragma unroll
            for (int rr = 0; rr < 4; rr++) {
                size_t row = qr0 + g + (rr & 1) * 8;
                int col = kc * 16 + (rr >> 1) * 8 + 2 * tig;
                q16[kc][rr] = *(const u32*)&g_q16[row * HD + col];
            }

        float of[8][4];
#pragma unroll
        for (int jn = 0; jn < 8; jn++)
#pragma unroll
            for (int r = 0; r < 4; r++) of[jn][r] = 0.f;
        float l0 = 0.f, l1 = 0.f;

        __syncthreads();   // prior half done with smem
        {
            const size_t kb0 = (size_t)b * SEQ;
#pragma unroll
            for (int l = 0; l < 8; l++) {
                int idx = tid + l * 128;
                int arr = idx >> 9, rem = idx & 511;
                int r = rem >> 3, c = rem & 7;
                u32 d = smb + (u32)arr * 8192 + (u32)r * 128 +
                        (u32)((c ^ (r & 7)) << 4);
                const __half* gp = (arr == 0) ? g_k16 : g_v16;
                cpasync16(d, gp + (kb0 + r) * HD + c * 8);
            }
            CP_COMMIT();
        }

#pragma unroll 1
        for (int kt = 0; kt < nkt; kt++) {
            CP_WAIT0();
            __syncthreads();
            const u32 buf = smb + (u32)(kt & 1) * 16384;
            if (kt + 1 < nkt) {
                const size_t kbn = (size_t)b * SEQ + (size_t)(kt + 1) * 64;
                const u32 nb = smb + (u32)((kt + 1) & 1) * 16384;
#pragma unroll
                for (int l = 0; l < 8; l++) {
                    int idx = tid + l * 128;
                    int arr = idx >> 9, rem = idx & 511;
                    int r = rem >> 3, c = rem & 7;
                    u32 d = nb + (u32)arr * 8192 + (u32)r * 128 +
                            (u32)((c ^ (r & 7)) << 4);
                    const __half* gp = (arr == 0) ? g_k16 : g_v16;
                    cpasync16(d, gp + (kbn + r) * HD + c * 8);
                }
                CP_COMMIT();
            }

            if (kt * 64 > w0 + 15) continue;   // warp fully above diagonal
            const bool dg = (kt * 64 + 63 > w0);

            u32 p16[4][4];
            // ---- S = q16 * K16 ; softmax (no max needed) ; pack P ----
#pragma unroll
            for (int j = 0; j < 8; j++) {
                float s[4] = {0.f, 0.f, 0.f, 0.f};
                u32 bh[8];
                {
                    u32 row = (u32)(j * 8 + (lane & 7));
                    u32 c16 = (u32)(lane >> 3);
                    ldsm4(bh, buf + row * 128 + ((c16 ^ (row & 7)) << 4));
                    ldsm4(bh + 4, buf + row * 128 + (((c16 + 4) ^ (row & 7)) << 4));
                }
#pragma unroll
                for (int kc = 0; kc < 4; kc++)
                    mma_f16(s, q16[kc], bh + 2 * kc);
                float p[4];
#pragma unroll
                for (int r = 0; r < 4; r++) {
                    float pv = ex2(s[r] * cfac);
                    if (dg) {
                        int key = kt * 64 + j * 8 + 2 * tig + (r & 1);
                        int qrl = w0 + g + ((r >> 1) << 3);
                        if (key > qrl) pv = 0.f;
                    }
                    p[r] = pv;
                }
                l0 += p[0] + p[1];
                l1 += p[2] + p[3];
                const int kc = j >> 1, hx = (j & 1) * 2;
                p16[kc][hx]     = packh16(p[0], p[1]);
                p16[kc][hx + 1] = packh16(p[2], p[3]);
            }

            // ---- O += P16 * V16 (single pass) ----
            const u32 vb = buf + 8192;
#pragma unroll
            for (int kc = 0; kc < 4; kc++)
#pragma unroll
                for (int jnp = 0; jnp < 4; jnp++) {
                    u32 vh[4];
                    u32 row = (u32)(kc * 16 + ((lane >> 3) & 1) * 8 + (lane & 7));
                    u32 c16 = (u32)(jnp * 2 + (lane >> 4));
                    u32 off = row * 128 + ((c16 ^ (row & 7)) << 4);
                    ldsm4t(vh, vb + off);
                    mma_f16(of[jnp * 2],     p16[kc], vh);
                    mma_f16(of[jnp * 2 + 1], p16[kc], vh + 2);
                }
        }

        // ---- epilogue ----
        l0 += __shfl_xor_sync(0xffffffffu, l0, 1);
        l0 += __shfl_xor_sync(0xffffffffu, l0, 2);
        l1 += __shfl_xor_sync(0xffffffffu, l1, 1);
        l1 += __shfl_xor_sync(0xffffffffu, l1, 2);
        const float inv0 = 1.0f / l0, inv1 = 1.0f / l1;

        const size_t orow0 = (qr0 + g) * HD;
        const size_t orow1 = orow0 + 8 * HD;
#pragma unroll
        for (int jn = 0; jn < 8; jn++) {
            int col = jn * 8 + 2 * tig;
            *(float2*)&out[orow0 + col] =
                make_float2(of[jn][0] * inv0, of[jn][1] * inv0);
            *(float2*)&out[orow1 + col] =
                make_float2(of[jn][2] * inv1, of[jn][3] * inv1);
        }
    }
}

// ---------------------------------------------------------------------------
extern "C" void kernel_launch(void* const* d_in, const int* in_sizes, int n_in,
                              void* d_out, int out_size)
{
    const float* x  = (const float*)d_in[0];
    const float* Wq = (const float*)d_in[1];
    const float* Wk = (const float*)d_in[2];
    const float* Wv = (const float*)d_in[3];
    float* out = (float*)d_out;

    cudaFuncSetAttribute(qkv_mma, cudaFuncAttributeMaxDynamicSharedMemorySize,
                         40960);
    cudaFuncSetAttribute(attn, cudaFuncAttributeMaxDynamicSharedMemorySize,
                         32768);

    split_w<<<384, 256>>>(Wq, Wk, Wv);
    qkv_mma<<<(BATCH * SEQ) / 64, 128, 40960>>>(x);
    attn<<<dim3(32, BATCH), 128, 32768>>>(out);
}